// round 4
// baseline (speedup 1.0000x reference)
#include <cuda_runtime.h>
#include <math.h>
#include <stdint.h>

#define N_ 512
#define L_ 65536
#define TWO_PI 6.283185307179586f
#define PI_F   3.14159265358979f
#define CAUCHY_BLOCKS 148
#define CHUNK 443            // ceil(65536/148)

// Scratch (allocation-free: __device__ globals)
// Duplicated-pair tables for lane-per-l f32x2 cauchy:
__device__ ulonglong2 d_P0[N_];  // (neg_lam_im dup, neg_lam_re dup)
__device__ ulonglong2 d_P1[N_];  // (t0r dup, t0i dup)
__device__ ulonglong2 d_P2[N_];  // (t1r dup, t1i dup)
__device__ ulonglong2 d_P3[N_];  // (t2r dup, t2i dup)
__device__ ulonglong2 d_P4[N_];  // (t3r dup, t3i dup)
__device__ float  d_gscale;      // 2/step
__device__ float2 d_atT[L_];     // atRoots, transposed: atT[a*256+b] = at[a+256b]
__device__ float2 d_stage[L_];   // FFT intermediate

__device__ __forceinline__ uint64_t pack2(float lo, float hi) {
    uint64_t r;
    asm("mov.b64 %0, {%1, %2};" : "=l"(r) : "r"(__float_as_uint(lo)), "r"(__float_as_uint(hi)));
    return r;
}
__device__ __forceinline__ void unpack2(uint64_t p, float& lo, float& hi) {
    uint32_t a, b;
    asm("mov.b64 {%0, %1}, %2;" : "=r"(a), "=r"(b) : "l"(p));
    lo = __uint_as_float(a); hi = __uint_as_float(b);
}
__device__ __forceinline__ uint64_t fma2(uint64_t a, uint64_t b, uint64_t c) {
    uint64_t d;
    asm("fma.rn.f32x2 %0, %1, %2, %3;" : "=l"(d) : "l"(a), "l"(b), "l"(c));
    return d;
}
__device__ __forceinline__ uint64_t add2(uint64_t a, uint64_t b) {
    uint64_t d;
    asm("add.rn.f32x2 %0, %1, %2;" : "=l"(d) : "l"(a), "l"(b));
    return d;
}
__device__ __forceinline__ uint64_t mul2(uint64_t a, uint64_t b) {
    uint64_t d;
    asm("mul.rn.f32x2 %0, %1, %2;" : "=l"(d) : "l"(a), "l"(b));
    return d;
}
__device__ __forceinline__ float frcp(float x) {
    float r; asm("rcp.approx.f32 %0, %1;" : "=f"(r) : "f"(x)); return r;
}

// ---------------------------------------------------------------------------
// Kernel 1: Bc = Vc @ B (one block per row, coalesced), duplicated tables.
// ---------------------------------------------------------------------------
__global__ void prep_kernel(const float* __restrict__ Lre, const float* __restrict__ Lim,
                            const float* __restrict__ pre, const float* __restrict__ pim,
                            const float* __restrict__ qre, const float* __restrict__ qim,
                            const float* __restrict__ Vre, const float* __restrict__ Vim,
                            const float* __restrict__ Ct,  const float* __restrict__ B,
                            const float* __restrict__ log_step) {
    int j = blockIdx.x;
    int t = threadIdx.x;

    const float* vr = Vre + j * N_;
    const float* vi = Vim + j * N_;
    float br = 0.f, bi = 0.f;
    #pragma unroll
    for (int i = t; i < N_; i += 128) {
        float b = __ldg(B + i);
        br += vr[i] * b;
        bi += vi[i] * b;
    }
    #pragma unroll
    for (int o = 16; o > 0; o >>= 1) {
        br += __shfl_down_sync(0xffffffffu, br, o);
        bi += __shfl_down_sync(0xffffffffu, bi, o);
    }
    __shared__ float sr[4], si[4];
    int w = t >> 5;
    if ((t & 31) == 0) { sr[w] = br; si[w] = bi; }
    __syncthreads();
    if (t == 0) {
        br = sr[0] + sr[1] + sr[2] + sr[3];
        bi = si[0] + si[1] + si[2] + si[3];

        // a0 = conj(Ct_c), a1 = conj(q), b0 = Bc, b1 = p
        float a0r = Ct[2 * j],  a0i = -Ct[2 * j + 1];
        float a1r = qre[j],     a1i = -qim[j];
        float b1r = pre[j],     b1i = pim[j];

        float t0r = a0r * br  - a0i * bi,  t0i = a0r * bi  + a0i * br;
        float t1r = a0r * b1r - a0i * b1i, t1i = a0r * b1i + a0i * b1r;
        float t2r = a1r * br  - a1i * bi,  t2i = a1r * bi  + a1i * br;
        float t3r = a1r * b1r - a1i * b1i, t3i = a1r * b1i + a1i * b1r;

        float lr = Lre[j], li = Lim[j];
        ulonglong2 v;
        v.x = pack2(-li, -li); v.y = pack2(-lr, -lr); d_P0[j] = v;
        v.x = pack2(t0r, t0r); v.y = pack2(t0i, t0i); d_P1[j] = v;
        v.x = pack2(t1r, t1r); v.y = pack2(t1i, t1i); d_P2[j] = v;
        v.x = pack2(t2r, t2r); v.y = pack2(t2i, t2i); d_P3[j] = v;
        v.x = pack2(t3r, t3r); v.y = pack2(t3i, t3i); d_P4[j] = v;
        if (j == 0) d_gscale = 2.0f / expf(log_step[0]);
    }
}

// ---------------------------------------------------------------------------
// Kernel 2: Cauchy reductions + low-rank correction -> atRoots (transposed).
// g = i*gs*tan(pi*l/L) purely imaginary; c = 1 + i*tan(pi*l/L).
// Lane-per-l f32x2: lanes (lo,hi) = (l, l+256). Balanced persistent grid.
// ---------------------------------------------------------------------------
__global__ void __launch_bounds__(256) cauchy_kernel() {
    __shared__ ulonglong2 sP0[N_];
    __shared__ ulonglong2 sP1[N_];
    __shared__ ulonglong2 sP2[N_];
    __shared__ ulonglong2 sP3[N_];
    __shared__ ulonglong2 sP4[N_];
    int t = threadIdx.x;
    #pragma unroll
    for (int i = t; i < N_; i += 256) {
        sP0[i] = d_P0[i];
        sP1[i] = d_P1[i];
        sP2[i] = d_P2[i];
        sP3[i] = d_P3[i];
        sP4[i] = d_P4[i];
    }
    __syncthreads();

    float gs = d_gscale;
    int start = blockIdx.x * CHUNK;
    int count = L_ - start; if (count > CHUNK) count = CHUNK;
    int l0 = start + t;
    int l1 = l0 + 256;
    bool act0 = (t < count);
    bool act1 = (t + 256 < count);

    float tanv[2];
    {
        float s, c;
        sincosf(PI_F * ((float)l0 * (1.0f / (float)L_)), &s, &c);
        tanv[0] = __fdividef(s, c);
        sincosf(PI_F * ((float)l1 * (1.0f / (float)L_)), &s, &c);
        tanv[1] = __fdividef(s, c);
    }
    uint64_t gi2 = pack2(gs * tanv[0], gs * tanv[1]);

    uint64_t k00r2 = 0, k00i2 = 0, k01r2 = 0, k01i2 = 0;
    uint64_t k10r2 = 0, k10i2 = 0, k11r2 = 0, k11i2 = 0;
    const uint64_t SGN2 = 0x8000000080000000ull;

    #pragma unroll 4
    for (int j = 0; j < N_; j++) {
        ulonglong2 P0 = sP0[j];
        ulonglong2 P1 = sP1[j];
        ulonglong2 P2 = sP2[j];
        ulonglong2 P3 = sP3[j];
        ulonglong2 P4 = sP4[j];
        uint64_t di2   = add2(gi2, P0.x);            // gi - lam_im
        uint64_t lrsq2 = mul2(P0.y, P0.y);           // lam_re^2
        uint64_t n2    = fma2(di2, di2, lrsq2);
        float nlo, nhi;
        unpack2(n2, nlo, nhi);
        uint64_t rinv2 = pack2(frcp(nlo), frcp(nhi));
        uint64_t rr2   = mul2(P0.y, rinv2);          // Re(r) = -lam_re/n
        uint64_t m2    = mul2(di2, rinv2);           // -Im(r) = di/n
        uint64_t nm2   = m2 ^ SGN2;                  // Im(r)

        // k_r += rr*t_r + m*t_i ; k_i += rr*t_i - m*t_r
        k00r2 = fma2(rr2, P1.x, k00r2);  k00r2 = fma2(m2,  P1.y, k00r2);
        k00i2 = fma2(rr2, P1.y, k00i2);  k00i2 = fma2(nm2, P1.x, k00i2);
        k01r2 = fma2(rr2, P2.x, k01r2);  k01r2 = fma2(m2,  P2.y, k01r2);
        k01i2 = fma2(rr2, P2.y, k01i2);  k01i2 = fma2(nm2, P2.x, k01i2);
        k10r2 = fma2(rr2, P3.x, k10r2);  k10r2 = fma2(m2,  P3.y, k10r2);
        k10i2 = fma2(rr2, P3.y, k10i2);  k10i2 = fma2(nm2, P3.x, k10i2);
        k11r2 = fma2(rr2, P4.x, k11r2);  k11r2 = fma2(m2,  P4.y, k11r2);
        k11i2 = fma2(rr2, P4.y, k11i2);  k11i2 = fma2(nm2, P4.x, k11i2);
    }

    float k00r[2], k00i[2], k01r[2], k01i[2], k10r[2], k10i[2], k11r[2], k11i[2];
    unpack2(k00r2, k00r[0], k00r[1]); unpack2(k00i2, k00i[0], k00i[1]);
    unpack2(k01r2, k01r[0], k01r[1]); unpack2(k01i2, k01i[0], k01i[1]);
    unpack2(k10r2, k10r[0], k10r[1]); unpack2(k10i2, k10i[0], k10i[1]);
    unpack2(k11r2, k11r[0], k11r[1]); unpack2(k11i2, k11i[0], k11i[1]);

    #pragma unroll
    for (int u = 0; u < 2; u++) {
        bool act = u ? act1 : act0;
        if (!act) continue;
        int l = u ? l1 : l0;
        // atRoots = (1 + i*tan) * (k00 - k01*k10/(1+k11))
        float ddr = 1.f + k11r[u], ddi = k11i[u];
        float dinv = __fdividef(1.f, ddr * ddr + ddi * ddi);
        float qr = k01r[u] * k10r[u] - k01i[u] * k10i[u];
        float qi = k01r[u] * k10i[u] + k01i[u] * k10r[u];
        float qdr = (qr * ddr + qi * ddi) * dinv;
        float qdi = (qi * ddr - qr * ddi) * dinv;
        float ar = k00r[u] - qdr;
        float ai = k00i[u] - qdi;
        float tv = tanv[u];
        d_atT[(l & 255) * 256 + (l >> 8)] =
            make_float2(ar - tv * ai, ai + tv * ar);
    }
}

// ---------------------------------------------------------------------------
// IFFT via four-step (L = 256 x 256), each 256-pt DFT radix-16 x 16,
// with each output split across 2 worker threads (block = 512).
// out[c + 256 d] = (1/L) sum_a W256^{ad} W_L^{ac} sum_b X[a + 256 b] W256^{bc}
// ---------------------------------------------------------------------------
__global__ void __launch_bounds__(512) fft_step1() {
    __shared__ float2 sx[256];
    __shared__ float2 sw[256];       // w[k] = e^{+2pi i k/256}
    __shared__ float2 sp[512];       // stage partials
    __shared__ float2 sz[16 * 17];   // padded
    int a = blockIdx.x, t = threadIdx.x;
    int h = t >> 8, r = t & 255;

    if (h == 0) {
        sx[r] = d_atT[a * 256 + r];
        float s, c;
        __sincosf(TWO_PI * ((float)r * (1.0f / 256.0f)), &s, &c);
        sw[r] = make_float2(c, s);
    }
    __syncthreads();

    // Stage A: z[b1][c1] = (sum_b2 x[b1+16b2] W16^{b2 c1}) * W256^{b1 c1}
    int b1 = r & 15, c1 = r >> 4;
    {
        float xr = 0.f, xi = 0.f;
        #pragma unroll
        for (int k = 0; k < 8; k++) {
            int b2 = 8 * h + k;
            float2 x = sx[b1 + 16 * b2];
            float2 w = sw[(16 * b2 * c1) & 255];
            xr += x.x * w.x - x.y * w.y;
            xi += x.x * w.y + x.y * w.x;
        }
        sp[t] = make_float2(xr, xi);
    }
    __syncthreads();
    if (h == 0) {
        float xr = sp[r].x + sp[r + 256].x;
        float xi = sp[r].y + sp[r + 256].y;
        float2 tw = sw[b1 * c1];
        sz[b1 * 17 + c1] = make_float2(xr * tw.x - xi * tw.y,
                                       xr * tw.y + xi * tw.x);
    }
    __syncthreads();

    // Stage B: Y[c1+16c2] = sum_b1 z[b1][c1] W16^{b1 c2};  output index = r
    {
        int oc1 = r & 15, oc2 = r >> 4;
        float yr = 0.f, yi = 0.f;
        #pragma unroll
        for (int k = 0; k < 8; k++) {
            int bb = 8 * h + k;
            float2 z = sz[bb * 17 + oc1];
            float2 w = sw[(16 * bb * oc2) & 255];
            yr += z.x * w.x - z.y * w.y;
            yi += z.x * w.y + z.y * w.x;
        }
        sp[t] = make_float2(yr, yi);
    }
    __syncthreads();
    if (h == 0) {
        float yr = sp[r].x + sp[r + 256].x;
        float yi = sp[r].y + sp[r + 256].y;
        int m = (a * r) & (L_ - 1);
        float ws, wc;
        __sincosf(TWO_PI * ((float)m * (1.0f / (float)L_)), &ws, &wc);
        d_stage[r * 256 + a] = make_float2(yr * wc - yi * ws,
                                           yr * ws + yi * wc);
    }
}

__global__ void __launch_bounds__(512) fft_step2(float* __restrict__ out) {
    __shared__ float2 sx[256];
    __shared__ float2 sw[256];
    __shared__ float2 sp[512];
    __shared__ float2 sz[16 * 17];
    int c = blockIdx.x, t = threadIdx.x;
    int h = t >> 8, r = t & 255;

    if (h == 0) {
        sx[r] = d_stage[c * 256 + r];
        float s, cc;
        __sincosf(TWO_PI * ((float)r * (1.0f / 256.0f)), &s, &cc);
        sw[r] = make_float2(cc, s);
    }
    __syncthreads();

    int a1 = r & 15, d1 = r >> 4;
    {
        float xr = 0.f, xi = 0.f;
        #pragma unroll
        for (int k = 0; k < 8; k++) {
            int a2 = 8 * h + k;
            float2 x = sx[a1 + 16 * a2];
            float2 w = sw[(16 * a2 * d1) & 255];
            xr += x.x * w.x - x.y * w.y;
            xi += x.x * w.y + x.y * w.x;
        }
        sp[t] = make_float2(xr, xi);
    }
    __syncthreads();
    if (h == 0) {
        float xr = sp[r].x + sp[r + 256].x;
        float xi = sp[r].y + sp[r + 256].y;
        float2 tw = sw[a1 * d1];
        sz[a1 * 17 + d1] = make_float2(xr * tw.x - xi * tw.y,
                                       xr * tw.y + xi * tw.x);
    }
    __syncthreads();

    {
        int od1 = r & 15, od2 = r >> 4;
        float yr = 0.f;    // only real part needed
        #pragma unroll
        for (int k = 0; k < 8; k++) {
            int aa = 8 * h + k;
            float2 z = sz[aa * 17 + od1];
            float2 w = sw[(16 * aa * od2) & 255];
            yr += z.x * w.x - z.y * w.y;
        }
        sp[t].x = yr;
    }
    __syncthreads();
    if (h == 0) {
        out[c + 256 * r] = (sp[r].x + sp[r + 256].x) * (1.0f / (float)L_);
    }
}

// ---------------------------------------------------------------------------
extern "C" void kernel_launch(void* const* d_in, const int* in_sizes, int n_in,
                              void* d_out, int out_size) {
    const float* Lambda_re = (const float*)d_in[0];
    const float* Lambda_im = (const float*)d_in[1];
    const float* p_re      = (const float*)d_in[2];
    const float* p_im      = (const float*)d_in[3];
    const float* q_re      = (const float*)d_in[4];
    const float* q_im      = (const float*)d_in[5];
    const float* Vc_re     = (const float*)d_in[6];
    const float* Vc_im     = (const float*)d_in[7];
    const float* Ct        = (const float*)d_in[8];
    const float* B         = (const float*)d_in[9];
    const float* log_step  = (const float*)d_in[10];
    float* out = (float*)d_out;

    prep_kernel<<<N_, 128>>>(Lambda_re, Lambda_im, p_re, p_im, q_re, q_im,
                             Vc_re, Vc_im, Ct, B, log_step);
    cauchy_kernel<<<CAUCHY_BLOCKS, 256>>>();
    fft_step1<<<256, 256 * 2>>>();
    fft_step2<<<256, 256 * 2>>>(out);
}

// round 5
// speedup vs baseline: 1.1503x; 1.1503x over previous
#include <cuda_runtime.h>
#include <math.h>
#include <stdint.h>

#define N_ 512
#define L_ 65536
#define M_ 32768
#define TWO_PI 6.283185307179586f
#define PI_F   3.14159265358979f

// Scratch (allocation-free: __device__ globals)
__device__ ulonglong2 d_P0[N_];  // (-lam_im dup, -lam_re dup)
__device__ ulonglong2 d_P1[N_];  // (t0r dup, t0i dup)
__device__ ulonglong2 d_P2[N_];  // (t1r dup, t1i dup)
__device__ ulonglong2 d_P3[N_];  // (t2r dup, t2i dup)
__device__ ulonglong2 d_P4[N_];  // (t3r dup, t3i dup)
__device__ uint64_t   d_Lr2[N_]; // (lam_re^2 dup)
__device__ float  d_gscale;      // 2/step
__device__ float2 d_at[L_];      // atRoots (natural order)
__device__ float2 d_stage[L_];   // FFT intermediate (only M_ used)

__device__ __forceinline__ uint64_t pack2(float lo, float hi) {
    uint64_t r;
    asm("mov.b64 %0, {%1, %2};" : "=l"(r) : "r"(__float_as_uint(lo)), "r"(__float_as_uint(hi)));
    return r;
}
__device__ __forceinline__ void unpack2(uint64_t p, float& lo, float& hi) {
    uint32_t a, b;
    asm("mov.b64 {%0, %1}, %2;" : "=r"(a), "=r"(b) : "l"(p));
    lo = __uint_as_float(a); hi = __uint_as_float(b);
}
__device__ __forceinline__ uint64_t fma2(uint64_t a, uint64_t b, uint64_t c) {
    uint64_t d;
    asm("fma.rn.f32x2 %0, %1, %2, %3;" : "=l"(d) : "l"(a), "l"(b), "l"(c));
    return d;
}
__device__ __forceinline__ uint64_t add2(uint64_t a, uint64_t b) {
    uint64_t d;
    asm("add.rn.f32x2 %0, %1, %2;" : "=l"(d) : "l"(a), "l"(b));
    return d;
}
__device__ __forceinline__ uint64_t mul2(uint64_t a, uint64_t b) {
    uint64_t d;
    asm("mul.rn.f32x2 %0, %1, %2;" : "=l"(d) : "l"(a), "l"(b));
    return d;
}
__device__ __forceinline__ float frcp(float x) {
    float r; asm("rcp.approx.f32 %0, %1;" : "=f"(r) : "f"(x)); return r;
}

// ---------------------------------------------------------------------------
// Kernel 1: Bc = Vc @ B (one block per row, coalesced), duplicated tables.
// ---------------------------------------------------------------------------
__global__ void prep_kernel(const float* __restrict__ Lre, const float* __restrict__ Lim,
                            const float* __restrict__ pre, const float* __restrict__ pim,
                            const float* __restrict__ qre, const float* __restrict__ qim,
                            const float* __restrict__ Vre, const float* __restrict__ Vim,
                            const float* __restrict__ Ct,  const float* __restrict__ B,
                            const float* __restrict__ log_step) {
    int j = blockIdx.x;
    int t = threadIdx.x;

    const float* vr = Vre + j * N_;
    const float* vi = Vim + j * N_;
    float br = 0.f, bi = 0.f;
    #pragma unroll
    for (int i = t; i < N_; i += 128) {
        float b = __ldg(B + i);
        br += vr[i] * b;
        bi += vi[i] * b;
    }
    #pragma unroll
    for (int o = 16; o > 0; o >>= 1) {
        br += __shfl_down_sync(0xffffffffu, br, o);
        bi += __shfl_down_sync(0xffffffffu, bi, o);
    }
    __shared__ float sr[4], si[4];
    int w = t >> 5;
    if ((t & 31) == 0) { sr[w] = br; si[w] = bi; }
    __syncthreads();
    if (t == 0) {
        br = sr[0] + sr[1] + sr[2] + sr[3];
        bi = si[0] + si[1] + si[2] + si[3];

        // a0 = conj(Ct_c), a1 = conj(q), b0 = Bc, b1 = p
        float a0r = Ct[2 * j],  a0i = -Ct[2 * j + 1];
        float a1r = qre[j],     a1i = -qim[j];
        float b1r = pre[j],     b1i = pim[j];

        float t0r = a0r * br  - a0i * bi,  t0i = a0r * bi  + a0i * br;
        float t1r = a0r * b1r - a0i * b1i, t1i = a0r * b1i + a0i * b1r;
        float t2r = a1r * br  - a1i * bi,  t2i = a1r * bi  + a1i * br;
        float t3r = a1r * b1r - a1i * b1i, t3i = a1r * b1i + a1i * b1r;

        float lr = Lre[j], li = Lim[j];
        ulonglong2 v;
        v.x = pack2(-li, -li); v.y = pack2(-lr, -lr); d_P0[j] = v;
        v.x = pack2(t0r, t0r); v.y = pack2(t0i, t0i); d_P1[j] = v;
        v.x = pack2(t1r, t1r); v.y = pack2(t1i, t1i); d_P2[j] = v;
        v.x = pack2(t2r, t2r); v.y = pack2(t2i, t2i); d_P3[j] = v;
        v.x = pack2(t3r, t3r); v.y = pack2(t3i, t3i); d_P4[j] = v;
        d_Lr2[j] = pack2(lr * lr, lr * lr);
        if (j == 0) d_gscale = 2.0f / expf(log_step[0]);
    }
}

// ---------------------------------------------------------------------------
// Kernel 2: Cauchy reductions + low-rank correction -> atRoots.
// g = i*gs*tan(pi*l/L) purely imaginary; c = 1 + i*tan(pi*l/L).
// Lane-per-l f32x2 (lanes = l, l+256). j-split across block halves for
// latency hiding (4 warps/SMSP); partials combined through smem.
// ---------------------------------------------------------------------------
__global__ void __launch_bounds__(512) cauchy_kernel() {
    __shared__ ulonglong2 sP0[N_];
    __shared__ ulonglong2 sP1[N_];
    __shared__ ulonglong2 sP2[N_];
    __shared__ ulonglong2 sP3[N_];
    __shared__ ulonglong2 sP4[N_];
    __shared__ uint64_t   sLr2[N_];
    int t = threadIdx.x;
    #pragma unroll
    for (int i = t; i < N_; i += 512) {
        sP0[i] = d_P0[i];
        sP1[i] = d_P1[i];
        sP2[i] = d_P2[i];
        sP3[i] = d_P3[i];
        sP4[i] = d_P4[i];
        sLr2[i] = d_Lr2[i];
    }
    __syncthreads();

    int h = t >> 8;          // j-half
    int r = t & 255;
    float gs = d_gscale;
    int l0 = blockIdx.x * 512 + r;
    int l1 = l0 + 256;

    float tan0, tan1;
    {
        float s, c;
        sincosf(PI_F * ((float)l0 * (1.0f / (float)L_)), &s, &c);
        tan0 = __fdividef(s, c);
        sincosf(PI_F * ((float)l1 * (1.0f / (float)L_)), &s, &c);
        tan1 = __fdividef(s, c);
    }
    uint64_t gi2 = pack2(gs * tan0, gs * tan1);

    uint64_t k00r2 = 0, k00i2 = 0, k01r2 = 0, k01i2 = 0;
    uint64_t k10r2 = 0, k10i2 = 0, k11r2 = 0, k11i2 = 0;
    const uint64_t SGN2 = 0x8000000080000000ull;

    int jbeg = h * 256, jend = jbeg + 256;
    #pragma unroll 4
    for (int j = jbeg; j < jend; j++) {
        ulonglong2 P0 = sP0[j];
        ulonglong2 P1 = sP1[j];
        ulonglong2 P2 = sP2[j];
        ulonglong2 P3 = sP3[j];
        ulonglong2 P4 = sP4[j];
        uint64_t lr2 = sLr2[j];
        uint64_t di2   = add2(gi2, P0.x);            // gi - lam_im
        uint64_t n2    = fma2(di2, di2, lr2);        // di^2 + lam_re^2
        float nlo, nhi;
        unpack2(n2, nlo, nhi);
        uint64_t rinv2 = pack2(frcp(nlo), frcp(nhi));
        uint64_t rr2   = mul2(P0.y, rinv2);          // Re(r) = -lam_re/n
        uint64_t m2    = mul2(di2, rinv2);           // -Im(r) = di/n
        uint64_t nm2   = m2 ^ SGN2;                  // Im(r)

        // k_r += rr*t_r + m*t_i ; k_i += rr*t_i + nm*t_r
        k00r2 = fma2(rr2, P1.x, k00r2);  k00r2 = fma2(m2,  P1.y, k00r2);
        k00i2 = fma2(rr2, P1.y, k00i2);  k00i2 = fma2(nm2, P1.x, k00i2);
        k01r2 = fma2(rr2, P2.x, k01r2);  k01r2 = fma2(m2,  P2.y, k01r2);
        k01i2 = fma2(rr2, P2.y, k01i2);  k01i2 = fma2(nm2, P2.x, k01i2);
        k10r2 = fma2(rr2, P3.x, k10r2);  k10r2 = fma2(m2,  P3.y, k10r2);
        k10i2 = fma2(rr2, P3.y, k10i2);  k10i2 = fma2(nm2, P3.x, k10i2);
        k11r2 = fma2(rr2, P4.x, k11r2);  k11r2 = fma2(m2,  P4.y, k11r2);
        k11i2 = fma2(rr2, P4.y, k11i2);  k11i2 = fma2(nm2, P4.x, k11i2);
    }

    // Combine j-halves: half 1 parks partials in (reused) table smem.
    __syncthreads();
    if (h == 1) {
        sP0[2 * r]     = make_ulonglong2(k00r2, k00i2);
        sP0[2 * r + 1] = make_ulonglong2(k01r2, k01i2);
        sP1[2 * r]     = make_ulonglong2(k10r2, k10i2);
        sP1[2 * r + 1] = make_ulonglong2(k11r2, k11i2);
    }
    __syncthreads();
    if (h == 0) {
        ulonglong2 v;
        v = sP0[2 * r];     k00r2 = add2(k00r2, v.x); k00i2 = add2(k00i2, v.y);
        v = sP0[2 * r + 1]; k01r2 = add2(k01r2, v.x); k01i2 = add2(k01i2, v.y);
        v = sP1[2 * r];     k10r2 = add2(k10r2, v.x); k10i2 = add2(k10i2, v.y);
        v = sP1[2 * r + 1]; k11r2 = add2(k11r2, v.x); k11i2 = add2(k11i2, v.y);

        float k00r[2], k00i[2], k01r[2], k01i[2], k10r[2], k10i[2], k11r[2], k11i[2];
        unpack2(k00r2, k00r[0], k00r[1]); unpack2(k00i2, k00i[0], k00i[1]);
        unpack2(k01r2, k01r[0], k01r[1]); unpack2(k01i2, k01i[0], k01i[1]);
        unpack2(k10r2, k10r[0], k10r[1]); unpack2(k10i2, k10i[0], k10i[1]);
        unpack2(k11r2, k11r[0], k11r[1]); unpack2(k11i2, k11i[0], k11i[1]);

        float tanv[2] = {tan0, tan1};
        #pragma unroll
        for (int u = 0; u < 2; u++) {
            int l = u ? l1 : l0;
            // atRoots = (1 + i*tan) * (k00 - k01*k10/(1+k11))
            float ddr = 1.f + k11r[u], ddi = k11i[u];
            float dinv = __fdividef(1.f, ddr * ddr + ddi * ddi);
            float qr = k01r[u] * k10r[u] - k01i[u] * k10i[u];
            float qi = k01r[u] * k10i[u] + k01i[u] * k10r[u];
            float qdr = (qr * ddr + qi * ddi) * dinv;
            float qdi = (qi * ddr - qr * ddi) * dinv;
            float ar = k00r[u] - qdr;
            float ai = k00i[u] - qdi;
            float tv = tanv[u];
            d_at[l] = make_float2(ar - tv * ai, ai + tv * ar);
        }
    }
}

// ---------------------------------------------------------------------------
// Real-output IFFT of length L via complex IFFT of length M = L/2 = 256x128.
//   G[k] = (X[k]+conj(X[L-k]))(1+i w_k) + (X[k+M]+conj(X[M-k]))(1-i w_k)
//   z = (1/(2L)) * sum_k G[k] e^{+2pi i k m / M};  out[2m]=Re z, out[2m+1]=Im z
// Four-step: k = a + 256 b (a in 256, b in 128); m = c + 128 d.
// ---------------------------------------------------------------------------
__global__ void __launch_bounds__(128) fft_step1() {
    __shared__ float2 sx[128];
    __shared__ float2 sw[128];       // e^{+2pi i k/128}
    __shared__ float2 sz[16 * 9];    // padded
    int a = blockIdx.x, t = threadIdx.x;   // t = b index

    // Build G[a + 256 t]
    {
        int k1 = a + 256 * t;
        float2 X1 = d_at[k1];
        float2 X2 = d_at[(L_ - k1) & (L_ - 1)];   // conj applied below
        float2 X3 = d_at[k1 + M_];
        float2 X4 = d_at[M_ - k1];
        float Ar = X1.x + X2.x, Ai = X1.y - X2.y;
        float Br = X3.x + X4.x, Bi = X3.y - X4.y;
        float ws, wc;
        __sincosf(TWO_PI * ((float)k1 * (1.0f / (float)L_)), &ws, &wc);
        float Qr = Ar - Br, Qi = Ai - Bi;
        float wqr = wc * Qr - ws * Qi;
        float wqi = wc * Qi + ws * Qr;
        sx[t] = make_float2(Ar + Br - wqi, Ai + Bi + wqr);
        float s, c;
        __sincosf(TWO_PI * ((float)t * (1.0f / 128.0f)), &s, &c);
        sw[t] = make_float2(c, s);
    }
    __syncthreads();

    // Stage A (radix over b2 in [0,8)): z[b1][c1], b1 in 16, c1 in 8
    {
        int b1 = t & 15, c1 = t >> 4;
        float xr = 0.f, xi = 0.f;
        #pragma unroll
        for (int b2 = 0; b2 < 8; b2++) {
            float2 x = sx[b1 + 16 * b2];
            float2 w = sw[(16 * b2 * c1) & 127];
            xr += x.x * w.x - x.y * w.y;
            xi += x.x * w.y + x.y * w.x;
        }
        float2 tw = sw[(b1 * c1) & 127];
        sz[b1 * 9 + c1] = make_float2(xr * tw.x - xi * tw.y,
                                      xr * tw.y + xi * tw.x);
    }
    __syncthreads();

    // Stage B: S[c1 + 8 c2] = sum_b1 z[b1][c1] W16^{b1 c2};  c = t
    {
        int c1 = t & 7, c2 = t >> 3;
        float yr = 0.f, yi = 0.f;
        #pragma unroll
        for (int b1 = 0; b1 < 16; b1++) {
            float2 z = sz[b1 * 9 + c1];
            float2 w = sw[(8 * b1 * c2) & 127];
            yr += z.x * w.x - z.y * w.y;
            yi += z.x * w.y + z.y * w.x;
        }
        int m = (a * t) & (M_ - 1);
        float ws, wc;
        __sincosf(TWO_PI * ((float)m * (1.0f / (float)M_)), &ws, &wc);
        d_stage[t * 256 + a] = make_float2(yr * wc - yi * ws,
                                           yr * ws + yi * wc);
    }
}

__global__ void __launch_bounds__(256) fft_step2(float2* __restrict__ out) {
    __shared__ float2 sx[256];
    __shared__ float2 sw[256];
    __shared__ float2 sz[16 * 17];
    int c = blockIdx.x, t = threadIdx.x;   // t = d index

    sx[t] = d_stage[c * 256 + t];
    {
        float s, cc;
        __sincosf(TWO_PI * ((float)t * (1.0f / 256.0f)), &s, &cc);
        sw[t] = make_float2(cc, s);
    }
    __syncthreads();

    {
        int a1 = t & 15, d1 = t >> 4;
        float xr = 0.f, xi = 0.f;
        #pragma unroll
        for (int a2 = 0; a2 < 16; a2++) {
            float2 x = sx[a1 + 16 * a2];
            float2 w = sw[(16 * a2 * d1) & 255];
            xr += x.x * w.x - x.y * w.y;
            xi += x.x * w.y + x.y * w.x;
        }
        float2 tw = sw[a1 * d1];
        sz[a1 * 17 + d1] = make_float2(xr * tw.x - xi * tw.y,
                                       xr * tw.y + xi * tw.x);
    }
    __syncthreads();

    {
        int d1 = t & 15, d2 = t >> 4;
        float yr = 0.f, yi = 0.f;
        #pragma unroll
        for (int a1 = 0; a1 < 16; a1++) {
            float2 z = sz[a1 * 17 + d1];
            float2 w = sw[(16 * a1 * d2) & 255];
            yr += z.x * w.x - z.y * w.y;
            yi += z.x * w.y + z.y * w.x;
        }
        const float sc = 1.0f / (2.0f * (float)L_);
        // m = c + 128*t ; out[2m], out[2m+1] = Re, Im  (float2 store)
        out[c + 128 * t] = make_float2(yr * sc, yi * sc);
    }
}

// ---------------------------------------------------------------------------
extern "C" void kernel_launch(void* const* d_in, const int* in_sizes, int n_in,
                              void* d_out, int out_size) {
    const float* Lambda_re = (const float*)d_in[0];
    const float* Lambda_im = (const float*)d_in[1];
    const float* p_re      = (const float*)d_in[2];
    const float* p_im      = (const float*)d_in[3];
    const float* q_re      = (const float*)d_in[4];
    const float* q_im      = (const float*)d_in[5];
    const float* Vc_re     = (const float*)d_in[6];
    const float* Vc_im     = (const float*)d_in[7];
    const float* Ct        = (const float*)d_in[8];
    const float* B         = (const float*)d_in[9];
    const float* log_step  = (const float*)d_in[10];

    prep_kernel<<<N_, 128>>>(Lambda_re, Lambda_im, p_re, p_im, q_re, q_im,
                             Vc_re, Vc_im, Ct, B, log_step);
    cauchy_kernel<<<L_ / 512, 512>>>();
    fft_step1<<<256, 128>>>();
    fft_step2<<<128, 256>>>((float2*)d_out);
}